// round 2
// baseline (speedup 1.0000x reference)
#include <cuda_runtime.h>
#include <math.h>

// Problem constants
#define B_   128
#define T_   2048
#define H_   200
#define NS_  5

// Scratch (static device globals — no dynamic allocation)
__device__ float g_qproj[B_ * H_];          // q@Wa^T + ba + bua
__device__ float g_scores[B_ * T_];         // scores -> attn (in place)
__device__ float g_ctxpart[8 * B_ * H_];    // partial context sums

__device__ __forceinline__ float sigm(float x) { return 1.0f / (1.0f + expf(-x)); }

// ---------------------------------------------------------------------------
// K0: q_proj[b][j] = sum_k h0[b][k]*Wa[j][k] + ba[j] + bua[j]
// ---------------------------------------------------------------------------
__global__ void k0_qproj(const float* __restrict__ h0, const float* __restrict__ Wa,
                         const float* __restrict__ ba, const float* __restrict__ bua) {
    int b = blockIdx.x, tid = threadIdx.x;
    __shared__ float hs[H_];
    for (int i = tid; i < H_; i += blockDim.x) hs[i] = h0[b * H_ + i];
    __syncthreads();
    for (int j = tid; j < H_; j += blockDim.x) {
        const float* w = Wa + j * H_;
        float acc = 0.f;
        #pragma unroll 4
        for (int k = 0; k < H_; k++) acc += hs[k] * w[k];
        g_qproj[b * H_ + j] = acc + ba[j] + bua[j];
    }
}

// ---------------------------------------------------------------------------
// K1: fused scores. For a 64-row tile of enc (rows of [B*T, H]):
//   kp[r][j] = sum_k enc[r][k] * Ua[j][k]
//   scores[r] = sum_j Va[j] * tanh(qproj[b][j] + kp[r][j])
// SGEMM register tiling: BM=64 rows, BN=200 (full), BK=8 (200 = 25*8 exact).
// 200 compute threads: tx in [0,25) -> 8 cols (two groups of 4, split at 100),
// ty in [0,8) -> 8 rows. Epilogue reduces over j inside the block.
// ---------------------------------------------------------------------------
#define BM 64
#define BK 8

__global__ __launch_bounds__(256, 2)
void k1_scores(const float* __restrict__ enc, const float* __restrict__ Ua,
               const float* __restrict__ Va) {
    __shared__ float enc_s[BK][BM];     // [k][row]
    __shared__ float ua_s[BK][H_];      // [k][j]
    __shared__ float qp_s[H_];
    __shared__ float va_s[H_];
    __shared__ float red[BM][26];

    int tid = threadIdx.x;
    int row0 = blockIdx.x * BM;
    int b = row0 >> 11;                 // T_ = 2048
    const float* encB = enc + (size_t)row0 * H_;

    for (int i = tid; i < H_; i += 256) {
        qp_s[i] = g_qproj[b * H_ + i];
        va_s[i] = Va[i];
    }

    int tx = tid % 25;
    int ty = tid / 25;
    bool compute = (tid < 200);

    float acc[8][8];
    #pragma unroll
    for (int i = 0; i < 8; i++)
        #pragma unroll
        for (int c = 0; c < 8; c++) acc[i][c] = 0.f;

    // enc tile load: 64 rows x 8 k = 256 float2, one per thread.
    int lr = tid >> 2;                  // row 0..63
    int lk = (tid & 3) * 2;             // k offset 0,2,4,6

    for (int k0 = 0; k0 < H_; k0 += BK) {
        {
            float2 v = *(const float2*)(encB + lr * H_ + k0 + lk);
            enc_s[lk + 0][lr] = v.x;
            enc_s[lk + 1][lr] = v.y;
        }
        // Ua tile: thread j<200 reads Ua[j][k0..k0+7] (two float4, 16B aligned:
        // j*200*4 % 16 == 0 and k0*4 % 32 == 0).
        if (tid < 200) {
            const float* u = Ua + tid * H_ + k0;
            float4 v0 = *(const float4*)(u);
            float4 v1 = *(const float4*)(u + 4);
            ua_s[0][tid] = v0.x; ua_s[1][tid] = v0.y;
            ua_s[2][tid] = v0.z; ua_s[3][tid] = v0.w;
            ua_s[4][tid] = v1.x; ua_s[5][tid] = v1.y;
            ua_s[6][tid] = v1.z; ua_s[7][tid] = v1.w;
        }
        __syncthreads();
        if (compute) {
            #pragma unroll
            for (int kk = 0; kk < BK; kk++) {
                float a[8], bb[8];
                #pragma unroll
                for (int i = 0; i < 8; i++) a[i] = enc_s[kk][ty * 8 + i];
                #pragma unroll
                for (int c = 0; c < 4; c++) {
                    bb[c]     = ua_s[kk][tx * 4 + c];
                    bb[4 + c] = ua_s[kk][100 + tx * 4 + c];
                }
                #pragma unroll
                for (int i = 0; i < 8; i++)
                    #pragma unroll
                    for (int c = 0; c < 8; c++) acc[i][c] += a[i] * bb[c];
            }
        }
        __syncthreads();
    }

    // Epilogue: tanh + Va-weighted reduction over j
    float part[8];
    #pragma unroll
    for (int i = 0; i < 8; i++) part[i] = 0.f;
    if (compute) {
        #pragma unroll
        for (int c = 0; c < 8; c++) {
            int j = (c < 4) ? (tx * 4 + c) : (100 + tx * 4 + (c - 4));
            float q = qp_s[j], v = va_s[j];
            #pragma unroll
            for (int i = 0; i < 8; i++)
                part[i] += v * tanhf(q + acc[i][c]);
        }
        #pragma unroll
        for (int i = 0; i < 8; i++) red[ty * 8 + i][tx] = part[i];
    }
    __syncthreads();
    if (tid < BM) {
        float s = 0.f;
        #pragma unroll
        for (int t = 0; t < 25; t++) s += red[tid][t];
        g_scores[row0 + tid] = s;
    }
}

// ---------------------------------------------------------------------------
// K2: softmax over T per batch, in place on g_scores.
// ---------------------------------------------------------------------------
__global__ void k2_softmax() {
    int b = blockIdx.x, tid = threadIdx.x;
    __shared__ float red[256];
    float* s = g_scores + b * T_;
    float m = -1e30f;
    for (int t = tid; t < T_; t += 256) m = fmaxf(m, s[t]);
    red[tid] = m;
    __syncthreads();
    for (int o = 128; o > 0; o >>= 1) {
        if (tid < o) red[tid] = fmaxf(red[tid], red[tid + o]);
        __syncthreads();
    }
    m = red[0];
    __syncthreads();
    float sum = 0.f;
    for (int t = tid; t < T_; t += 256) {
        float e = expf(s[t] - m);
        s[t] = e;
        sum += e;
    }
    red[tid] = sum;
    __syncthreads();
    for (int o = 128; o > 0; o >>= 1) {
        if (tid < o) red[tid] += red[tid + o];
        __syncthreads();
    }
    float inv = 1.0f / red[0];
    for (int t = tid; t < T_; t += 256) s[t] *= inv;
}

// ---------------------------------------------------------------------------
// K3: context partials. grid (B, 8); each block handles 256 t's.
// ---------------------------------------------------------------------------
__global__ void k3_context(const float* __restrict__ enc) {
    int b = blockIdx.x, sp = blockIdx.y, tid = threadIdx.x;
    __shared__ float at[256];
    int t0 = sp * 256;
    at[tid] = g_scores[b * T_ + t0 + tid];
    __syncthreads();
    if (tid < H_) {
        const float* e = enc + ((size_t)b * T_ + t0) * H_ + tid;
        float a0 = 0.f, a1 = 0.f, a2 = 0.f, a3 = 0.f;
        for (int t = 0; t < 256; t += 4) {
            a0 += at[t + 0] * e[(size_t)(t + 0) * H_];
            a1 += at[t + 1] * e[(size_t)(t + 1) * H_];
            a2 += at[t + 2] * e[(size_t)(t + 2) * H_];
            a3 += at[t + 3] * e[(size_t)(t + 3) * H_];
        }
        g_ctxpart[(sp * B_ + b) * H_ + tid] = (a0 + a1) + (a2 + a3);
    }
}

// ---------------------------------------------------------------------------
// K4: decode. One block per batch. gates_base constant across steps; only the
// scalar x (= previous y) changes. 5 sequential steps in-block.
// ---------------------------------------------------------------------------
__global__ void k4_decode(const float* __restrict__ x_in, const float* __restrict__ h0,
                          const float* __restrict__ c0,
                          const float* __restrict__ W_ih, const float* __restrict__ W_hh,
                          const float* __restrict__ b_ih, const float* __restrict__ b_hh,
                          const float* __restrict__ W1, const float* __restrict__ b1,
                          const float* __restrict__ W2, const float* __restrict__ b2,
                          const float* __restrict__ W3, const float* __restrict__ b3,
                          float* __restrict__ out) {
    int b = blockIdx.x, tid = threadIdx.x;
    __shared__ float ctx[H_], h0s[H_], c0s[H_];
    __shared__ float gb[4 * H_], wcol[4 * H_];
    __shared__ float hr[H_], o1[100], o2[50];
    __shared__ float xs;

    for (int i = tid; i < H_; i += 256) {
        float cacc = 0.f;
        #pragma unroll
        for (int sp = 0; sp < 8; sp++) cacc += g_ctxpart[(sp * B_ + b) * H_ + i];
        ctx[i] = cacc;
        h0s[i] = h0[b * H_ + i];
        c0s[i] = c0[b * H_ + i];
    }
    __syncthreads();

    // gates_base[j] = b_ih + b_hh + h0 @ W_hh[j] + ctx @ W_ih[j][1:]
    for (int j = tid; j < 4 * H_; j += 256) {
        const float* whh = W_hh + j * H_;
        const float* wih = W_ih + j * (H_ + 1);
        float acc = b_ih[j] + b_hh[j];
        #pragma unroll 4
        for (int k = 0; k < H_; k++) acc += h0s[k] * whh[k] + ctx[k] * wih[1 + k];
        gb[j] = acc;
        wcol[j] = wih[0];
    }
    if (tid == 0) xs = x_in[b];
    __syncthreads();

    for (int s = 0; s < NS_; s++) {
        float x = xs;
        if (tid < H_) {
            int j = tid;
            float gi = gb[j]           + x * wcol[j];
            float gf = gb[H_ + j]      + x * wcol[H_ + j];
            float gg = gb[2 * H_ + j]  + x * wcol[2 * H_ + j];
            float go = gb[3 * H_ + j]  + x * wcol[3 * H_ + j];
            float c = sigm(gf) * c0s[j] + sigm(gi) * tanhf(gg);
            float h = sigm(go) * tanhf(c);
            hr[j] = fmaxf(h, 0.f);
        }
        __syncthreads();
        if (tid < 100) {
            const float* w = W1 + tid * H_;
            float a = b1[tid];
            #pragma unroll 4
            for (int k = 0; k < H_; k++) a += w[k] * hr[k];
            o1[tid] = fmaxf(a, 0.f);
        }
        __syncthreads();
        if (tid < 50) {
            const float* w = W2 + tid * 100;
            float a = b2[tid];
            #pragma unroll 4
            for (int k = 0; k < 100; k++) a += w[k] * o1[k];
            o2[tid] = fmaxf(a, 0.f);
        }
        __syncthreads();
        if (tid == 0) {
            float a = b3[0];
            #pragma unroll
            for (int k = 0; k < 50; k++) a += W3[k] * o2[k];
            out[b * NS_ + s] = a;
            xs = a;
        }
        __syncthreads();
    }
}

// ---------------------------------------------------------------------------
extern "C" void kernel_launch(void* const* d_in, const int* in_sizes, int n_in,
                              void* d_out, int out_size) {
    const float* x    = (const float*)d_in[0];
    const float* h0   = (const float*)d_in[1];
    const float* c0   = (const float*)d_in[2];
    const float* enc  = (const float*)d_in[3];
    const float* Wa   = (const float*)d_in[4];
    const float* ba   = (const float*)d_in[5];
    const float* Ua   = (const float*)d_in[6];
    const float* bua  = (const float*)d_in[7];
    const float* Va   = (const float*)d_in[8];
    // d_in[9] = bva: constant shift of scores, softmax-invariant -> unused.
    const float* W_ih = (const float*)d_in[10];
    const float* W_hh = (const float*)d_in[11];
    const float* b_ih = (const float*)d_in[12];
    const float* b_hh = (const float*)d_in[13];
    const float* W1   = (const float*)d_in[14];
    const float* b1   = (const float*)d_in[15];
    const float* W2   = (const float*)d_in[16];
    const float* b2   = (const float*)d_in[17];
    const float* W3   = (const float*)d_in[18];
    const float* b3   = (const float*)d_in[19];
    float* out = (float*)d_out;

    k0_qproj<<<B_, 256>>>(h0, Wa, ba, bua);
    k1_scores<<<(B_ * T_) / BM, 256>>>(enc, Ua, Va);
    k2_softmax<<<B_, 256>>>();
    k3_context<<<dim3(B_, 8), 256>>>(enc);
    k4_decode<<<B_, 256>>>(x, h0, c0, W_ih, W_hh, b_ih, b_hh,
                           W1, b1, W2, b2, W3, b3, out);
}

// round 3
// speedup vs baseline: 1.0996x; 1.0996x over previous
#include <cuda_runtime.h>
#include <math.h>

// Problem constants
#define B_   128
#define T_   2048
#define H_   200
#define NS_  5

#define BM 64
#define BK 8
#define TILES_PER_B (T_ / BM)           // 32
#define NTILES (B_ * TILES_PER_B)       // 4096

// Scratch (static device globals — no dynamic allocation)
__device__ float g_qproj[B_ * H_];            // q@Wa^T + ba + bua
__device__ float g_ctxpart[NTILES * H_];      // per-tile exp-weighted enc sums
__device__ float g_denpart[NTILES];           // per-tile exp sums
__device__ float g_ctx[B_ * H_];              // normalized context

__device__ __forceinline__ float sigm(float x) { return 1.0f / (1.0f + expf(-x)); }

__device__ __forceinline__ float tanh_fast(float x) {
    float y;
    asm("tanh.approx.f32 %0, %1;" : "=f"(y) : "f"(x));
    return y;
}

typedef unsigned long long ull;

__device__ __forceinline__ ull ffma2(ull a, ull b, ull c) {
    ull d;
    asm("fma.rn.f32x2 %0, %1, %2, %3;" : "=l"(d) : "l"(a), "l"(b), "l"(c));
    return d;
}
__device__ __forceinline__ ull dup2(float x) {
    ull d;
    asm("mov.b64 %0, {%1, %1};" : "=l"(d) : "f"(x));
    return d;
}
__device__ __forceinline__ float lo2(ull v) { return __uint_as_float((unsigned)(v & 0xffffffffULL)); }
__device__ __forceinline__ float hi2(ull v) { return __uint_as_float((unsigned)(v >> 32)); }

// ---------------------------------------------------------------------------
// K0: q_proj[b][j] = sum_k h0[b][k]*Wa[j][k] + ba[j] + bua[j]
// ---------------------------------------------------------------------------
__global__ void k0_qproj(const float* __restrict__ h0, const float* __restrict__ Wa,
                         const float* __restrict__ ba, const float* __restrict__ bua) {
    int b = blockIdx.x, tid = threadIdx.x;
    __shared__ float hs[H_];
    for (int i = tid; i < H_; i += blockDim.x) hs[i] = h0[b * H_ + i];
    __syncthreads();
    for (int j = tid; j < H_; j += blockDim.x) {
        const float* w = Wa + j * H_;
        float acc = 0.f;
        #pragma unroll 4
        for (int k = 0; k < H_; k++) acc += hs[k] * w[k];
        g_qproj[b * H_ + j] = acc + ba[j] + bua[j];
    }
}

// ---------------------------------------------------------------------------
// K1: fused scores + exp + partial context.
//   kp[r][j] = sum_k enc[r][k] * Ua[j][k]
//   score[r] = sum_j Va[j] * tanh(qproj[b][j] + kp[r][j])
//   e[r] = exp(score[r])           (no max subtraction: |score| <= ||Va||_1)
//   ctxpart[tile][k] = sum_r e[r] * enc[r][k] ; denpart[tile] = sum_r e[r]
// GEMM via packed fma.rn.f32x2: 8 rows x 4 column-pairs per compute thread.
// ---------------------------------------------------------------------------
__global__ __launch_bounds__(256, 2)
void k1_scores(const float* __restrict__ enc, const float* __restrict__ Ua,
               const float* __restrict__ Va) {
    __shared__ float enc_s[BK][BM];     // [k][row]
    __shared__ float ua_s[BK][H_];      // [k][j]
    __shared__ float qp_s[H_];
    __shared__ float va_s[H_];
    __shared__ float red[BM][26];
    __shared__ float es[BM];

    int tid = threadIdx.x;
    int row0 = blockIdx.x * BM;
    int b = row0 >> 11;                 // T_ = 2048
    const float* encB = enc + (size_t)row0 * H_;

    for (int i = tid; i < H_; i += 256) {
        qp_s[i] = g_qproj[b * H_ + i];
        va_s[i] = Va[i];
    }

    int tx = tid % 25;
    int ty = tid / 25;
    bool compute = (tid < 200);

    ull acc2[8][4];
    #pragma unroll
    for (int i = 0; i < 8; i++)
        #pragma unroll
        for (int p = 0; p < 4; p++) acc2[i][p] = 0ULL;

    // enc tile load: 64 rows x 8 k = 256 float2, one per thread.
    int lr = tid >> 2;                  // row 0..63
    int lk = (tid & 3) * 2;             // k offset 0,2,4,6

    for (int k0 = 0; k0 < H_; k0 += BK) {
        {
            float2 v = *(const float2*)(encB + lr * H_ + k0 + lk);
            enc_s[lk + 0][lr] = v.x;
            enc_s[lk + 1][lr] = v.y;
        }
        if (tid < 200) {
            const float* u = Ua + tid * H_ + k0;
            float4 v0 = *(const float4*)(u);
            float4 v1 = *(const float4*)(u + 4);
            ua_s[0][tid] = v0.x; ua_s[1][tid] = v0.y;
            ua_s[2][tid] = v0.z; ua_s[3][tid] = v0.w;
            ua_s[4][tid] = v1.x; ua_s[5][tid] = v1.y;
            ua_s[6][tid] = v1.z; ua_s[7][tid] = v1.w;
        }
        __syncthreads();
        if (compute) {
            #pragma unroll
            for (int kk = 0; kk < BK; kk++) {
                ull a2[8], b2[4];
                #pragma unroll
                for (int i = 0; i < 8; i++) a2[i] = dup2(enc_s[kk][ty * 8 + i]);
                {
                    float2 p0 = *(const float2*)&ua_s[kk][tx * 4];
                    float2 p1 = *(const float2*)&ua_s[kk][tx * 4 + 2];
                    float2 p2 = *(const float2*)&ua_s[kk][100 + tx * 4];
                    float2 p3 = *(const float2*)&ua_s[kk][100 + tx * 4 + 2];
                    b2[0] = *(const ull*)&p0;
                    b2[1] = *(const ull*)&p1;
                    b2[2] = *(const ull*)&p2;
                    b2[3] = *(const ull*)&p3;
                }
                #pragma unroll
                for (int i = 0; i < 8; i++)
                    #pragma unroll
                    for (int p = 0; p < 4; p++)
                        acc2[i][p] = ffma2(a2[i], b2[p], acc2[i][p]);
            }
        }
        __syncthreads();
    }

    // Epilogue 1: tanh + Va-weighted reduction over j -> scores
    if (compute) {
        float part[8];
        #pragma unroll
        for (int i = 0; i < 8; i++) part[i] = 0.f;
        #pragma unroll
        for (int p = 0; p < 4; p++) {
            int j0 = (p < 2) ? (tx * 4 + p * 2) : (100 + tx * 4 + (p - 2) * 2);
            float qlo = qp_s[j0],     vlo = va_s[j0];
            float qhi = qp_s[j0 + 1], vhi = va_s[j0 + 1];
            #pragma unroll
            for (int i = 0; i < 8; i++) {
                part[i] += vlo * tanh_fast(qlo + lo2(acc2[i][p]));
                part[i] += vhi * tanh_fast(qhi + hi2(acc2[i][p]));
            }
        }
        #pragma unroll
        for (int i = 0; i < 8; i++) red[ty * 8 + i][tx] = part[i];
    }
    __syncthreads();
    if (tid < BM) {
        float s = 0.f;
        #pragma unroll
        for (int t = 0; t < 25; t++) s += red[tid][t];
        es[tid] = expf(s);
    }
    __syncthreads();

    // Epilogue 2: partial context (re-read enc tile; L2-hot) + denom
    if (tid < H_) {
        const float* e = encB + tid;
        float a0 = 0.f, a1 = 0.f, a2 = 0.f, a3 = 0.f;
        #pragma unroll 4
        for (int r = 0; r < BM; r += 4) {
            a0 += es[r + 0] * e[(r + 0) * H_];
            a1 += es[r + 1] * e[(r + 1) * H_];
            a2 += es[r + 2] * e[(r + 2) * H_];
            a3 += es[r + 3] * e[(r + 3) * H_];
        }
        g_ctxpart[blockIdx.x * H_ + tid] = (a0 + a1) + (a2 + a3);
    } else if (tid == 224) {
        float s = 0.f;
        #pragma unroll 8
        for (int r = 0; r < BM; r++) s += es[r];
        g_denpart[blockIdx.x] = s;
    }
}

// ---------------------------------------------------------------------------
// K2: reduce partials -> normalized context. One block per batch.
// ---------------------------------------------------------------------------
__global__ void k2_reduce() {
    int b = blockIdx.x, tid = threadIdx.x;
    __shared__ float dsum;
    if (tid == 0) {
        float s = 0.f;
        #pragma unroll
        for (int t = 0; t < TILES_PER_B; t++) s += g_denpart[b * TILES_PER_B + t];
        dsum = 1.0f / s;
    }
    __syncthreads();
    if (tid < H_) {
        float a = 0.f;
        #pragma unroll
        for (int t = 0; t < TILES_PER_B; t++)
            a += g_ctxpart[(b * TILES_PER_B + t) * H_ + tid];
        g_ctx[b * H_ + tid] = a * dsum;
    }
}

// ---------------------------------------------------------------------------
// K4: decode. One block per batch. gates_base constant across steps; only the
// scalar x (= previous y) changes. 5 sequential steps in-block.
// ---------------------------------------------------------------------------
__global__ void k4_decode(const float* __restrict__ x_in, const float* __restrict__ h0,
                          const float* __restrict__ c0,
                          const float* __restrict__ W_ih, const float* __restrict__ W_hh,
                          const float* __restrict__ b_ih, const float* __restrict__ b_hh,
                          const float* __restrict__ W1, const float* __restrict__ b1,
                          const float* __restrict__ W2, const float* __restrict__ b2,
                          const float* __restrict__ W3, const float* __restrict__ b3,
                          float* __restrict__ out) {
    int b = blockIdx.x, tid = threadIdx.x;
    __shared__ float ctx[H_], h0s[H_], c0s[H_];
    __shared__ float gb[4 * H_], wcol[4 * H_];
    __shared__ float hr[H_], o1[100], o2[50];
    __shared__ float xs;

    for (int i = tid; i < H_; i += 256) {
        ctx[i] = g_ctx[b * H_ + i];
        h0s[i] = h0[b * H_ + i];
        c0s[i] = c0[b * H_ + i];
    }
    __syncthreads();

    // gates_base[j] = b_ih + b_hh + h0 @ W_hh[j] + ctx @ W_ih[j][1:]
    for (int j = tid; j < 4 * H_; j += 256) {
        const float* whh = W_hh + j * H_;
        const float* wih = W_ih + j * (H_ + 1);
        float acc = b_ih[j] + b_hh[j];
        #pragma unroll 4
        for (int k = 0; k < H_; k++) acc += h0s[k] * whh[k] + ctx[k] * wih[1 + k];
        gb[j] = acc;
        wcol[j] = wih[0];
    }
    if (tid == 0) xs = x_in[b];
    __syncthreads();

    for (int s = 0; s < NS_; s++) {
        float x = xs;
        if (tid < H_) {
            int j = tid;
            float gi = gb[j]           + x * wcol[j];
            float gf = gb[H_ + j]      + x * wcol[H_ + j];
            float gg = gb[2 * H_ + j]  + x * wcol[2 * H_ + j];
            float go = gb[3 * H_ + j]  + x * wcol[3 * H_ + j];
            float c = sigm(gf) * c0s[j] + sigm(gi) * tanhf(gg);
            float h = sigm(go) * tanhf(c);
            hr[j] = fmaxf(h, 0.f);
        }
        __syncthreads();
        if (tid < 100) {
            const float* w = W1 + tid * H_;
            float a = b1[tid];
            #pragma unroll 4
            for (int k = 0; k < H_; k++) a += w[k] * hr[k];
            o1[tid] = fmaxf(a, 0.f);
        }
        __syncthreads();
        if (tid < 50) {
            const float* w = W2 + tid * 100;
            float a = b2[tid];
            #pragma unroll 4
            for (int k = 0; k < 100; k++) a += w[k] * o1[k];
            o2[tid] = fmaxf(a, 0.f);
        }
        __syncthreads();
        if (tid == 0) {
            float a = b3[0];
            #pragma unroll
            for (int k = 0; k < 50; k++) a += W3[k] * o2[k];
            out[b * NS_ + s] = a;
            xs = a;
        }
        __syncthreads();
    }
}

// ---------------------------------------------------------------------------
extern "C" void kernel_launch(void* const* d_in, const int* in_sizes, int n_in,
                              void* d_out, int out_size) {
    const float* x    = (const float*)d_in[0];
    const float* h0   = (const float*)d_in[1];
    const float* c0   = (const float*)d_in[2];
    const float* enc  = (const float*)d_in[3];
    const float* Wa   = (const float*)d_in[4];
    const float* ba   = (const float*)d_in[5];
    const float* Ua   = (const float*)d_in[6];
    const float* bua  = (const float*)d_in[7];
    const float* Va   = (const float*)d_in[8];
    // d_in[9] = bva: constant shift of scores, softmax-invariant -> unused.
    const float* W_ih = (const float*)d_in[10];
    const float* W_hh = (const float*)d_in[11];
    const float* b_ih = (const float*)d_in[12];
    const float* b_hh = (const float*)d_in[13];
    const float* W1   = (const float*)d_in[14];
    const float* b1   = (const float*)d_in[15];
    const float* W2   = (const float*)d_in[16];
    const float* b2   = (const float*)d_in[17];
    const float* W3   = (const float*)d_in[18];
    const float* b3   = (const float*)d_in[19];
    float* out = (float*)d_out;

    k0_qproj<<<B_, 256>>>(h0, Wa, ba, bua);
    k1_scores<<<NTILES, 256>>>(enc, Ua, Va);
    k2_reduce<<<B_, 256>>>();
    k4_decode<<<B_, 256>>>(x, h0, c0, W_ih, W_hh, b_ih, b_hh,
                           W1, b1, W2, b2, W3, b3, out);
}